// round 2
// baseline (speedup 1.0000x reference)
#include <cuda_runtime.h>
#include <math.h>

// Problem constants
#define Bc  4
#define Sc  2048
#define Dc  1024
#define Hc  16
#define HDc 64
#define Fc  4096
#define Nc  2048

// ---------------- scratch (__device__ globals; no cudaMalloc allowed) ----------------
__device__ float g_sel[Nc * Dc];
__device__ float g_h[Nc * Dc];
__device__ float g_cg[Nc * HDc];
__device__ float g_sg[Nc * HDc];
__device__ float g_q[Nc * Dc];
__device__ float g_k[Nc * Dc];
__device__ float g_v[Nc * Dc];
__device__ float g_S[(size_t)Hc * Nc * Nc];   // 256 MB: scores, then probs (in-place)
__device__ float g_ctx[Nc * Dc];
__device__ float g_h2[Nc * Dc];
__device__ float g_m[Nc * Dc];
__device__ float g_gate[Nc * Fc];
__device__ float g_up[Nc * Fc];               // after silu kernel holds act = silu(g)*u
__device__ float g_proc[Nc * Dc];

// ---------------- gather + RMSNorm(ln1), plus cos/sin gather ----------------
__global__ __launch_bounds__(256) void gather_norm_kernel(
    const float* __restrict__ hidden, const int* __restrict__ bi,
    const int* __restrict__ ti, const float* __restrict__ cosp,
    const float* __restrict__ sinp, const float* __restrict__ ln1)
{
    int n = blockIdx.x;
    int b = bi[n], t = ti[n];
    const float* row = hidden + ((size_t)b * Sc + t) * Dc;
    float vals[4];
    float local = 0.f;
#pragma unroll
    for (int i = 0; i < 4; i++) {
        float x = row[threadIdx.x + 256 * i];
        vals[i] = x;
        local += x * x;
    }
    __shared__ float red[256];
    red[threadIdx.x] = local;
    __syncthreads();
    for (int s = 128; s > 0; s >>= 1) {
        if (threadIdx.x < s) red[threadIdx.x] += red[threadIdx.x + s];
        __syncthreads();
    }
    float inv = rsqrtf(red[0] / (float)Dc + 1e-6f);
#pragma unroll
    for (int i = 0; i < 4; i++) {
        int d = threadIdx.x + 256 * i;
        g_sel[(size_t)n * Dc + d] = vals[i];
        g_h[(size_t)n * Dc + d] = vals[i] * inv * ln1[d];
    }
    if (threadIdx.x < HDc) {
        size_t src = ((size_t)b * Sc + t) * HDc + threadIdx.x;
        g_cg[n * HDc + threadIdx.x] = cosp[src];
        g_sg[n * HDc + threadIdx.x] = sinp[src];
    }
}

// ---------------- RMSNorm(ln2): g_h2 -> g_m ----------------
__global__ __launch_bounds__(256) void rmsnorm2_kernel(const float* __restrict__ ln2)
{
    int n = blockIdx.x;
    const float* row = g_h2 + (size_t)n * Dc;
    float vals[4];
    float local = 0.f;
#pragma unroll
    for (int i = 0; i < 4; i++) {
        float x = row[threadIdx.x + 256 * i];
        vals[i] = x;
        local += x * x;
    }
    __shared__ float red[256];
    red[threadIdx.x] = local;
    __syncthreads();
    for (int s = 128; s > 0; s >>= 1) {
        if (threadIdx.x < s) red[threadIdx.x] += red[threadIdx.x + s];
        __syncthreads();
    }
    float inv = rsqrtf(red[0] / (float)Dc + 1e-6f);
#pragma unroll
    for (int i = 0; i < 4; i++) {
        int d = threadIdx.x + 256 * i;
        g_m[(size_t)n * Dc + d] = vals[i] * inv * ln2[d];
    }
}

// ---------------- generic tiled SGEMM: C_w = A @ B_w (+bias_w) (+res) ----------------
// Tile: 128(M) x 64(N), BK=16, 256 threads, each thread 8x4.
// Supports up to 3 weight matrices side-by-side in grid.y (QKV / gate-up fusion).
__global__ __launch_bounds__(256) void sgemm_kernel(
    const float* __restrict__ A, int K,
    const float* __restrict__ B0, const float* __restrict__ B1, const float* __restrict__ B2,
    const float* __restrict__ bias0, const float* __restrict__ bias1, const float* __restrict__ bias2,
    const float* __restrict__ res,
    float* __restrict__ C0, float* __restrict__ C1, float* __restrict__ C2,
    int ldo, int blocksPerW)
{
    int bm = blockIdx.x;
    int by = blockIdx.y;
    int w  = by / blocksPerW;
    int cb = by % blocksPerW;
    const float* B    = (w == 0) ? B0    : (w == 1) ? B1    : B2;
    const float* bias = (w == 0) ? bias0 : (w == 1) ? bias1 : bias2;
    float*       C    = (w == 0) ? C0    : (w == 1) ? C1    : C2;

    __shared__ float As[16][132];  // transposed [k][m], padded
    __shared__ float Bs[16][64];   // [k][n]

    int tid = threadIdx.x;
    int tx = tid & 15;   // 0..15 -> 4 output cols each
    int ty = tid >> 4;   // 0..15 -> 8 output rows each

    float acc[8][4];
#pragma unroll
    for (int i = 0; i < 8; i++)
#pragma unroll
        for (int j = 0; j < 4; j++) acc[i][j] = 0.f;

    const float* Ablk = A + (size_t)bm * 128 * K;
    const float* Bblk = B + cb * 64;

    for (int kt = 0; kt < K; kt += 16) {
        // load A tile 128x16 (2 float4 per thread), store transposed
#pragma unroll
        for (int f = 0; f < 2; f++) {
            int fi = tid + 256 * f;
            int row = fi >> 2;
            int c4 = fi & 3;
            float4 v = *(const float4*)&Ablk[(size_t)row * K + kt + c4 * 4];
            As[c4 * 4 + 0][row] = v.x;
            As[c4 * 4 + 1][row] = v.y;
            As[c4 * 4 + 2][row] = v.z;
            As[c4 * 4 + 3][row] = v.w;
        }
        // load B tile 16x64 (1 float4 per thread)
        {
            int row = tid >> 4;
            int c4 = tid & 15;
            float4 v = *(const float4*)&Bblk[(size_t)(kt + row) * ldo + c4 * 4];
            *(float4*)&Bs[row][c4 * 4] = v;
        }
        __syncthreads();
#pragma unroll
        for (int k = 0; k < 16; k++) {
            float4 a0 = *(float4*)&As[k][ty * 8];
            float4 a1 = *(float4*)&As[k][ty * 8 + 4];
            float4 b  = *(float4*)&Bs[k][tx * 4];
            float av[8] = {a0.x, a0.y, a0.z, a0.w, a1.x, a1.y, a1.z, a1.w};
            float bv[4] = {b.x, b.y, b.z, b.w};
#pragma unroll
            for (int i = 0; i < 8; i++)
#pragma unroll
                for (int j = 0; j < 4; j++) acc[i][j] = fmaf(av[i], bv[j], acc[i][j]);
        }
        __syncthreads();
    }

    int col0 = cb * 64 + tx * 4;
#pragma unroll
    for (int i = 0; i < 8; i++) {
        int r = bm * 128 + ty * 8 + i;
        float4 o;
        o.x = acc[i][0]; o.y = acc[i][1]; o.z = acc[i][2]; o.w = acc[i][3];
        if (bias) {
            o.x += bias[col0 + 0]; o.y += bias[col0 + 1];
            o.z += bias[col0 + 2]; o.w += bias[col0 + 3];
        }
        if (res) {
            const float* rr = res + (size_t)r * ldo + col0;
            o.x += rr[0]; o.y += rr[1]; o.z += rr[2]; o.w += rr[3];
        }
        *(float4*)&C[(size_t)r * ldo + col0] = o;
    }
}

// ---------------- RoPE in-place on g_q and g_k ----------------
__global__ __launch_bounds__(256) void rope_kernel()
{
    int idx = blockIdx.x * blockDim.x + threadIdx.x;   // 2 * N * H * 32 total
    int total = Nc * Hc * 32;
    float* buf = (idx < total) ? g_q : g_k;
    int r = idx % total;
    int n = r / (Hc * 32);
    int rem = r % (Hc * 32);
    int h = rem >> 5;
    int d = rem & 31;
    float c1 = g_cg[n * HDc + d],      s1 = g_sg[n * HDc + d];
    float c2 = g_cg[n * HDc + d + 32], s2 = g_sg[n * HDc + d + 32];
    float* p = buf + (size_t)n * Dc + h * HDc;
    float x1 = p[d], x2 = p[d + 32];
    p[d]      = x1 * c1 - x2 * s1;
    p[d + 32] = x2 * c2 + x1 * s2;
}

// ---------------- scores: S[h][n][m] = (q_n . k_m)/8, lower-triangular tiles only ----------------
__global__ __launch_bounds__(256) void scores_kernel()
{
    int qt = blockIdx.x, kt = blockIdx.y, h = blockIdx.z;
    if (kt > qt) return;
    __shared__ float Qs[64][68];   // [d][token]
    __shared__ float Ks[64][68];
    int tid = threadIdx.x;
#pragma unroll
    for (int r = 0; r < 16; r++) {
        int idx = tid + 256 * r;
        int tok = idx >> 6;
        int d = idx & 63;
        Qs[d][tok] = g_q[(size_t)(qt * 64 + tok) * Dc + h * HDc + d];
        Ks[d][tok] = g_k[(size_t)(kt * 64 + tok) * Dc + h * HDc + d];
    }
    __syncthreads();
    int tx = tid & 15, ty = tid >> 4;
    float acc[4][4];
#pragma unroll
    for (int i = 0; i < 4; i++)
#pragma unroll
        for (int j = 0; j < 4; j++) acc[i][j] = 0.f;
#pragma unroll 8
    for (int d = 0; d < 64; d++) {
        float4 a = *(float4*)&Qs[d][ty * 4];
        float4 b = *(float4*)&Ks[d][tx * 4];
        float av[4] = {a.x, a.y, a.z, a.w};
        float bv[4] = {b.x, b.y, b.z, b.w};
#pragma unroll
        for (int i = 0; i < 4; i++)
#pragma unroll
            for (int j = 0; j < 4; j++) acc[i][j] = fmaf(av[i], bv[j], acc[i][j]);
    }
    float* out = g_S + ((size_t)h * Nc + qt * 64) * Nc + kt * 64;
#pragma unroll
    for (int i = 0; i < 4; i++) {
        float4 o;
        o.x = acc[i][0] * 0.125f; o.y = acc[i][1] * 0.125f;
        o.z = acc[i][2] * 0.125f; o.w = acc[i][3] * 0.125f;
        *(float4*)&out[(size_t)(ty * 4 + i) * Nc + tx * 4] = o;
    }
}

// ---------------- causal softmax, in-place on g_S; zero-fill above diagonal ----------------
__global__ __launch_bounds__(128) void softmax_kernel()
{
    int n = blockIdx.x, h = blockIdx.y;
    float* row = g_S + ((size_t)h * Nc + n) * Nc;
    int len = n + 1;
    __shared__ float red[128];
    int tid = threadIdx.x;

    float mx = -3.4e38f;
    for (int i = tid; i < len; i += 128) mx = fmaxf(mx, row[i]);
    red[tid] = mx;
    __syncthreads();
    for (int s = 64; s > 0; s >>= 1) {
        if (tid < s) red[tid] = fmaxf(red[tid], red[tid + s]);
        __syncthreads();
    }
    mx = red[0];
    __syncthreads();

    float sum = 0.f;
    for (int i = tid; i < len; i += 128) sum += expf(row[i] - mx);
    red[tid] = sum;
    __syncthreads();
    for (int s = 64; s > 0; s >>= 1) {
        if (tid < s) red[tid] += red[tid + s];
        __syncthreads();
    }
    float inv = 1.f / red[0];

    for (int i = tid; i < Nc; i += 128)
        row[i] = (i < len) ? expf(row[i] - mx) * inv : 0.f;
}

// ---------------- ctx[n][h][:] = sum_m P[h][n][m] * v[m][h][:], causal-bounded K loop ----------------
__global__ __launch_bounds__(256) void ctx_kernel()
{
    int qt = blockIdx.x, h = blockIdx.y;
    __shared__ float Ps[64][33];   // [row][k]
    __shared__ float Vs[32][68];   // [k][d]
    int tid = threadIdx.x;
    int tx = tid & 15, ty = tid >> 4;
    float acc[4][4];
#pragma unroll
    for (int i = 0; i < 4; i++)
#pragma unroll
        for (int j = 0; j < 4; j++) acc[i][j] = 0.f;

    int ktiles = 2 * qt + 2;   // columns [0, (qt+1)*64) in steps of 32
    const float* Pbase = g_S + ((size_t)h * Nc + qt * 64) * Nc;

    for (int kt = 0; kt < ktiles; kt++) {
#pragma unroll
        for (int r = 0; r < 8; r++) {
            int idx = tid + 256 * r;
            int rr = idx >> 5;
            int kk = idx & 31;
            Ps[rr][kk] = Pbase[(size_t)rr * Nc + kt * 32 + kk];
        }
#pragma unroll
        for (int r = 0; r < 8; r++) {
            int idx = tid + 256 * r;
            int tok = idx >> 6;
            int d = idx & 63;
            Vs[tok][d] = g_v[(size_t)(kt * 32 + tok) * Dc + h * HDc + d];
        }
        __syncthreads();
#pragma unroll
        for (int kk = 0; kk < 32; kk++) {
            float av[4];
#pragma unroll
            for (int i = 0; i < 4; i++) av[i] = Ps[ty * 4 + i][kk];
            float4 b = *(float4*)&Vs[kk][tx * 4];
            float bv[4] = {b.x, b.y, b.z, b.w};
#pragma unroll
            for (int i = 0; i < 4; i++)
#pragma unroll
                for (int j = 0; j < 4; j++) acc[i][j] = fmaf(av[i], bv[j], acc[i][j]);
        }
        __syncthreads();
    }
#pragma unroll
    for (int i = 0; i < 4; i++) {
        int n = qt * 64 + ty * 4 + i;
        float4 o;
        o.x = acc[i][0]; o.y = acc[i][1]; o.z = acc[i][2]; o.w = acc[i][3];
        *(float4*)&g_ctx[(size_t)n * Dc + h * HDc + tx * 4] = o;
    }
}

// ---------------- act = silu(gate) * up, into g_up ----------------
__global__ __launch_bounds__(256) void silu_kernel()
{
    int idx = blockIdx.x * blockDim.x + threadIdx.x;
    float a = g_gate[idx];
    float s = a / (1.f + expf(-a));
    g_up[idx] = s * g_up[idx];
}

// ---------------- out[b,t,:] = sel + gate_n * (proc - sel) ----------------
__global__ __launch_bounds__(256) void scatter_kernel(
    const int* __restrict__ bi, const int* __restrict__ ti,
    const float* __restrict__ gs, float* __restrict__ out)
{
    int idx = blockIdx.x * blockDim.x + threadIdx.x;   // N*D
    int n = idx >> 10;
    int d = idx & 1023;
    int b = bi[n], t = ti[n];
    float sel = g_sel[idx];
    float p = g_proc[idx];
    out[((size_t)b * Sc + t) * Dc + d] = sel + gs[n] * (p - sel);
}

// ---------------- driver ----------------
extern "C" void kernel_launch(void* const* d_in, const int* in_sizes, int n_in,
                              void* d_out, int out_size)
{
    const float* hidden = (const float*)d_in[0];
    const int*   bi     = (const int*)d_in[1];
    const int*   ti     = (const int*)d_in[2];
    const float* gs     = (const float*)d_in[3];
    const float* cosp   = (const float*)d_in[4];
    const float* sinp   = (const float*)d_in[5];
    const float* Wq     = (const float*)d_in[6];
    const float* bq     = (const float*)d_in[7];
    const float* Wk     = (const float*)d_in[8];
    const float* bk     = (const float*)d_in[9];
    const float* Wv     = (const float*)d_in[10];
    const float* bv     = (const float*)d_in[11];
    const float* Wo     = (const float*)d_in[12];
    const float* Wg     = (const float*)d_in[13];
    const float* Wu     = (const float*)d_in[14];
    const float* Wd     = (const float*)d_in[15];
    const float* ln1    = (const float*)d_in[16];
    const float* ln2    = (const float*)d_in[17];
    float* out = (float*)d_out;

    // cache __device__ symbol addresses (first call is the non-capture correctness call)
    static float *p_sel = nullptr, *p_h = nullptr, *p_q = nullptr, *p_k = nullptr,
                 *p_v = nullptr, *p_ctx = nullptr, *p_h2 = nullptr, *p_m = nullptr,
                 *p_gate = nullptr, *p_up = nullptr, *p_proc = nullptr;
    if (!p_sel) {
        cudaGetSymbolAddress((void**)&p_sel, g_sel);
        cudaGetSymbolAddress((void**)&p_h, g_h);
        cudaGetSymbolAddress((void**)&p_q, g_q);
        cudaGetSymbolAddress((void**)&p_k, g_k);
        cudaGetSymbolAddress((void**)&p_v, g_v);
        cudaGetSymbolAddress((void**)&p_ctx, g_ctx);
        cudaGetSymbolAddress((void**)&p_h2, g_h2);
        cudaGetSymbolAddress((void**)&p_m, g_m);
        cudaGetSymbolAddress((void**)&p_gate, g_gate);
        cudaGetSymbolAddress((void**)&p_up, g_up);
        cudaGetSymbolAddress((void**)&p_proc, g_proc);
    }

    // 1) copy hidden -> out (scatter overwrites selected rows later)
    cudaMemcpyAsync(out, hidden, sizeof(float) * Bc * Sc * Dc, cudaMemcpyDeviceToDevice);

    // 2) gather + rmsnorm(ln1) + cos/sin gather
    gather_norm_kernel<<<Nc, 256>>>(hidden, bi, ti, cosp, sinp, ln1);

    // 3) QKV fused GEMM: h @ {Wq,Wk,Wv} + bias
    sgemm_kernel<<<dim3(16, 48), 256>>>(p_h, Dc, Wq, Wk, Wv, bq, bk, bv, nullptr,
                                        p_q, p_k, p_v, Dc, 16);

    // 4) RoPE on q and k
    rope_kernel<<<(2 * Nc * Hc * 32) / 256, 256>>>();

    // 5) scores (lower-triangular tiles)
    scores_kernel<<<dim3(32, 32, Hc), 256>>>();

    // 6) causal softmax in-place
    softmax_kernel<<<dim3(Nc, Hc), 128>>>();

    // 7) ctx = P @ V (causal-bounded)
    ctx_kernel<<<dim3(32, Hc), 256>>>();

    // 8) h2 = sel + ctx @ Wo
    sgemm_kernel<<<dim3(16, 16), 256>>>(p_ctx, Dc, Wo, Wo, Wo,
                                        nullptr, nullptr, nullptr, p_sel,
                                        p_h2, p_h2, p_h2, Dc, 16);

    // 9) m = rmsnorm(h2, ln2)
    rmsnorm2_kernel<<<Nc, 256>>>(ln2);

    // 10) gate/up fused GEMM: m @ {Wg, Wu}
    sgemm_kernel<<<dim3(16, 128), 256>>>(p_m, Dc, Wg, Wu, Wu,
                                         nullptr, nullptr, nullptr, nullptr,
                                         p_gate, p_up, p_up, Fc, 64);

    // 11) act = silu(gate) * up  (into g_up)
    silu_kernel<<<(Nc * Fc) / 256, 256>>>();

    // 12) proc = h2 + act @ Wd
    sgemm_kernel<<<dim3(16, 16), 256>>>(p_up, Fc, Wd, Wd, Wd,
                                        nullptr, nullptr, nullptr, p_h2,
                                        p_proc, p_proc, p_proc, Dc, 16);

    // 13) gated scatter back
    scatter_kernel<<<(Nc * Dc) / 256, 256>>>(bi, ti, gs, out);
}

// round 3
// speedup vs baseline: 1.8847x; 1.8847x over previous
#include <cuda_runtime.h>
#include <math.h>
#include <stdint.h>

// Problem constants
#define Bc  4
#define Sc  2048
#define Dc  1024
#define Hc  16
#define HDc 64
#define Fc  4096
#define Nc  2048

// ---------------- scratch (__device__ globals; no cudaMalloc allowed) ----------------
__device__ float g_sel[Nc * Dc];
__device__ float g_h[Nc * Dc];
__device__ float g_cg[Nc * HDc];
__device__ float g_sg[Nc * HDc];
__device__ float g_q[Nc * Dc];
__device__ float g_k[Nc * Dc];
__device__ float g_v[Nc * Dc];
__device__ float g_S[(size_t)Hc * Nc * Nc];   // 256 MB: scores, then probs (in-place)
__device__ float g_ctx[Nc * Dc];
__device__ float g_h2[Nc * Dc];
__device__ float g_m[Nc * Dc];
__device__ float g_gate[Nc * Fc];
__device__ float g_up[Nc * Fc];               // after silu kernel holds act = silu(g)*u
__device__ float g_proc[Nc * Dc];

// ---------------- tf32 helpers ----------------
__device__ __forceinline__ uint32_t f2tf32(float x) {
    uint32_t r;
    asm("cvt.rna.tf32.f32 %0, %1;" : "=r"(r) : "f"(x));
    return r;
}

__device__ __forceinline__ void mma_tf32(float* c, const uint32_t* a, const uint32_t* b) {
    asm volatile(
        "mma.sync.aligned.m16n8k8.row.col.f32.tf32.tf32.f32 "
        "{%0,%1,%2,%3}, {%4,%5,%6,%7}, {%8,%9}, {%0,%1,%2,%3};"
        : "+f"(c[0]), "+f"(c[1]), "+f"(c[2]), "+f"(c[3])
        : "r"(a[0]), "r"(a[1]), "r"(a[2]), "r"(a[3]), "r"(b[0]), "r"(b[1]));
}

// ---------------- gather + RMSNorm(ln1), plus cos/sin gather ----------------
__global__ __launch_bounds__(256) void gather_norm_kernel(
    const float* __restrict__ hidden, const int* __restrict__ bi,
    const int* __restrict__ ti, const float* __restrict__ cosp,
    const float* __restrict__ sinp, const float* __restrict__ ln1)
{
    int n = blockIdx.x;
    int b = bi[n], t = ti[n];
    const float* row = hidden + ((size_t)b * Sc + t) * Dc;
    float vals[4];
    float local = 0.f;
#pragma unroll
    for (int i = 0; i < 4; i++) {
        float x = row[threadIdx.x + 256 * i];
        vals[i] = x;
        local += x * x;
    }
    __shared__ float red[256];
    red[threadIdx.x] = local;
    __syncthreads();
    for (int s = 128; s > 0; s >>= 1) {
        if (threadIdx.x < s) red[threadIdx.x] += red[threadIdx.x + s];
        __syncthreads();
    }
    float inv = rsqrtf(red[0] / (float)Dc + 1e-6f);
#pragma unroll
    for (int i = 0; i < 4; i++) {
        int d = threadIdx.x + 256 * i;
        g_sel[(size_t)n * Dc + d] = vals[i];
        g_h[(size_t)n * Dc + d] = vals[i] * inv * ln1[d];
    }
    if (threadIdx.x < HDc) {
        size_t src = ((size_t)b * Sc + t) * HDc + threadIdx.x;
        g_cg[n * HDc + threadIdx.x] = cosp[src];
        g_sg[n * HDc + threadIdx.x] = sinp[src];
    }
}

// ---------------- RMSNorm(ln2): g_h2 -> g_m ----------------
__global__ __launch_bounds__(256) void rmsnorm2_kernel(const float* __restrict__ ln2)
{
    int n = blockIdx.x;
    const float* row = g_h2 + (size_t)n * Dc;
    float vals[4];
    float local = 0.f;
#pragma unroll
    for (int i = 0; i < 4; i++) {
        float x = row[threadIdx.x + 256 * i];
        vals[i] = x;
        local += x * x;
    }
    __shared__ float red[256];
    red[threadIdx.x] = local;
    __syncthreads();
    for (int s = 128; s > 0; s >>= 1) {
        if (threadIdx.x < s) red[threadIdx.x] += red[threadIdx.x + s];
        __syncthreads();
    }
    float inv = rsqrtf(red[0] / (float)Dc + 1e-6f);
#pragma unroll
    for (int i = 0; i < 4; i++) {
        int d = threadIdx.x + 256 * i;
        g_m[(size_t)n * Dc + d] = vals[i] * inv * ln2[d];
    }
}

// ---------------- tf32 tensor-core GEMM: C_w = A @ B_w (+bias_w) (+res) ----------------
// Block tile 128x128, BK=32, 256 threads (8 warps, warp grid 2x4, warp tile 64x32).
// A smem [m][36] and B smem [k][136] layouts give conflict-free fragment loads.
// Supports up to 3 weight matrices side-by-side via grid.y (QKV / gate-up fusion).
__global__ __launch_bounds__(256) void tgemm_kernel(
    const float* __restrict__ A, int K,
    const float* __restrict__ B0, const float* __restrict__ B1, const float* __restrict__ B2,
    const float* __restrict__ bias0, const float* __restrict__ bias1, const float* __restrict__ bias2,
    const float* __restrict__ res,
    float* __restrict__ C0, float* __restrict__ C1, float* __restrict__ C2,
    int ldo, int blocksPerW)
{
    int bm = blockIdx.x;
    int by = blockIdx.y;
    int w  = by / blocksPerW;
    int cb = by % blocksPerW;
    const float* B    = (w == 0) ? B0    : (w == 1) ? B1    : B2;
    const float* bias = (w == 0) ? bias0 : (w == 1) ? bias1 : bias2;
    float*       C    = (w == 0) ? C0    : (w == 1) ? C1    : C2;

    __shared__ uint32_t As[128][36];   // [m][k], pad -> stride%32==4
    __shared__ uint32_t Bs[32][136];   // [k][n], pad -> stride%32==8

    int tid = threadIdx.x;
    int lane = tid & 31;
    int warp = tid >> 5;
    int warpM = warp & 1;       // 2 warps along M
    int warpN = warp >> 1;      // 4 warps along N
    int qr = lane >> 2;         // 0..7
    int qc = lane & 3;          // 0..3

    float acc[4][4][4];
#pragma unroll
    for (int mi = 0; mi < 4; mi++)
#pragma unroll
        for (int ni = 0; ni < 4; ni++)
#pragma unroll
            for (int j = 0; j < 4; j++) acc[mi][ni][j] = 0.f;

    const float* Ablk = A + (size_t)bm * 128 * K;
    const float* Bblk = B + cb * 128;

    for (int kt = 0; kt < K; kt += 32) {
        // A tile: 128x32 -> 1024 float4, 4 per thread; cvt to tf32 at store
#pragma unroll
        for (int i = 0; i < 4; i++) {
            int idx = tid + 256 * i;
            int row = idx >> 3;
            int c4 = idx & 7;
            float4 v = *(const float4*)&Ablk[(size_t)row * K + kt + c4 * 4];
            As[row][c4 * 4 + 0] = f2tf32(v.x);
            As[row][c4 * 4 + 1] = f2tf32(v.y);
            As[row][c4 * 4 + 2] = f2tf32(v.z);
            As[row][c4 * 4 + 3] = f2tf32(v.w);
        }
        // B tile: 32x128 -> 1024 float4, 4 per thread
#pragma unroll
        for (int i = 0; i < 4; i++) {
            int idx = tid + 256 * i;
            int row = idx >> 5;
            int c4 = idx & 31;
            float4 v = *(const float4*)&Bblk[(size_t)(kt + row) * ldo + c4 * 4];
            Bs[row][c4 * 4 + 0] = f2tf32(v.x);
            Bs[row][c4 * 4 + 1] = f2tf32(v.y);
            Bs[row][c4 * 4 + 2] = f2tf32(v.z);
            Bs[row][c4 * 4 + 3] = f2tf32(v.w);
        }
        __syncthreads();

#pragma unroll
        for (int kk = 0; kk < 4; kk++) {
            int k0 = kk * 8;
            uint32_t a[4][4], b[4][2];
#pragma unroll
            for (int mi = 0; mi < 4; mi++) {
                int r0 = warpM * 64 + mi * 16 + qr;
                a[mi][0] = As[r0][k0 + qc];
                a[mi][1] = As[r0 + 8][k0 + qc];
                a[mi][2] = As[r0][k0 + qc + 4];
                a[mi][3] = As[r0 + 8][k0 + qc + 4];
            }
#pragma unroll
            for (int ni = 0; ni < 4; ni++) {
                int nn = warpN * 32 + ni * 8 + qr;
                b[ni][0] = Bs[k0 + qc][nn];
                b[ni][1] = Bs[k0 + qc + 4][nn];
            }
#pragma unroll
            for (int mi = 0; mi < 4; mi++)
#pragma unroll
                for (int ni = 0; ni < 4; ni++)
                    mma_tf32(acc[mi][ni], a[mi], b[ni]);
        }
        __syncthreads();
    }

    // epilogue: c0,c1 at (row, col..col+1); c2,c3 at (row+8, col..col+1)
#pragma unroll
    for (int mi = 0; mi < 4; mi++) {
#pragma unroll
        for (int ni = 0; ni < 4; ni++) {
            int row = bm * 128 + warpM * 64 + mi * 16 + qr;
            int col = cb * 128 + warpN * 32 + ni * 8 + 2 * qc;
            float2 lo, hi;
            lo.x = acc[mi][ni][0]; lo.y = acc[mi][ni][1];
            hi.x = acc[mi][ni][2]; hi.y = acc[mi][ni][3];
            if (bias) {
                float b0 = bias[col], b1 = bias[col + 1];
                lo.x += b0; lo.y += b1; hi.x += b0; hi.y += b1;
            }
            if (res) {
                const float* r0 = res + (size_t)row * ldo + col;
                const float* r1 = res + (size_t)(row + 8) * ldo + col;
                lo.x += r0[0]; lo.y += r0[1];
                hi.x += r1[0]; hi.y += r1[1];
            }
            *(float2*)&C[(size_t)row * ldo + col] = lo;
            *(float2*)&C[(size_t)(row + 8) * ldo + col] = hi;
        }
    }
}

// ---------------- RoPE in-place on g_q and g_k ----------------
__global__ __launch_bounds__(256) void rope_kernel()
{
    int idx = blockIdx.x * blockDim.x + threadIdx.x;   // 2 * N * H * 32 total
    int total = Nc * Hc * 32;
    float* buf = (idx < total) ? g_q : g_k;
    int r = idx % total;
    int n = r / (Hc * 32);
    int rem = r % (Hc * 32);
    int h = rem >> 5;
    int d = rem & 31;
    float c1 = g_cg[n * HDc + d],      s1 = g_sg[n * HDc + d];
    float c2 = g_cg[n * HDc + d + 32], s2 = g_sg[n * HDc + d + 32];
    float* p = buf + (size_t)n * Dc + h * HDc;
    float x1 = p[d], x2 = p[d + 32];
    p[d]      = x1 * c1 - x2 * s1;
    p[d + 32] = x2 * c2 + x1 * s2;
}

// ---------------- scores: S[h][n][m] = (q_n . k_m)/8, lower-triangular tiles only ----------------
__global__ __launch_bounds__(256) void scores_kernel()
{
    int qt = blockIdx.x, kt = blockIdx.y, h = blockIdx.z;
    if (kt > qt) return;
    __shared__ float Qs[64][68];   // [d][token]
    __shared__ float Ks[64][68];
    int tid = threadIdx.x;
#pragma unroll
    for (int r = 0; r < 16; r++) {
        int idx = tid + 256 * r;
        int tok = idx >> 6;
        int d = idx & 63;
        Qs[d][tok] = g_q[(size_t)(qt * 64 + tok) * Dc + h * HDc + d];
        Ks[d][tok] = g_k[(size_t)(kt * 64 + tok) * Dc + h * HDc + d];
    }
    __syncthreads();
    int tx = tid & 15, ty = tid >> 4;
    float acc[4][4];
#pragma unroll
    for (int i = 0; i < 4; i++)
#pragma unroll
        for (int j = 0; j < 4; j++) acc[i][j] = 0.f;
#pragma unroll 8
    for (int d = 0; d < 64; d++) {
        float4 a = *(float4*)&Qs[d][ty * 4];
        float4 b = *(float4*)&Ks[d][tx * 4];
        float av[4] = {a.x, a.y, a.z, a.w};
        float bv[4] = {b.x, b.y, b.z, b.w};
#pragma unroll
        for (int i = 0; i < 4; i++)
#pragma unroll
            for (int j = 0; j < 4; j++) acc[i][j] = fmaf(av[i], bv[j], acc[i][j]);
    }
    float* out = g_S + ((size_t)h * Nc + qt * 64) * Nc + kt * 64;
#pragma unroll
    for (int i = 0; i < 4; i++) {
        float4 o;
        o.x = acc[i][0] * 0.125f; o.y = acc[i][1] * 0.125f;
        o.z = acc[i][2] * 0.125f; o.w = acc[i][3] * 0.125f;
        *(float4*)&out[(size_t)(ty * 4 + i) * Nc + tx * 4] = o;
    }
}

// ---------------- causal softmax, in-place on g_S; zero-fill above diagonal ----------------
__global__ __launch_bounds__(128) void softmax_kernel()
{
    int n = blockIdx.x, h = blockIdx.y;
    float* row = g_S + ((size_t)h * Nc + n) * Nc;
    int len = n + 1;
    __shared__ float red[128];
    int tid = threadIdx.x;

    float mx = -3.4e38f;
    for (int i = tid; i < len; i += 128) mx = fmaxf(mx, row[i]);
    red[tid] = mx;
    __syncthreads();
    for (int s = 64; s > 0; s >>= 1) {
        if (tid < s) red[tid] = fmaxf(red[tid], red[tid + s]);
        __syncthreads();
    }
    mx = red[0];
    __syncthreads();

    float sum = 0.f;
    for (int i = tid; i < len; i += 128) sum += expf(row[i] - mx);
    red[tid] = sum;
    __syncthreads();
    for (int s = 64; s > 0; s >>= 1) {
        if (tid < s) red[tid] += red[tid + s];
        __syncthreads();
    }
    float inv = 1.f / red[0];

    for (int i = tid; i < Nc; i += 128)
        row[i] = (i < len) ? expf(row[i] - mx) * inv : 0.f;
}

// ---------------- ctx[n][h][:] = sum_m P[h][n][m] * v[m][h][:], causal-bounded K loop ----------------
__global__ __launch_bounds__(256) void ctx_kernel()
{
    int qt = blockIdx.x, h = blockIdx.y;
    __shared__ float Ps[64][33];   // [row][k]
    __shared__ float Vs[32][68];   // [k][d]
    int tid = threadIdx.x;
    int tx = tid & 15, ty = tid >> 4;
    float acc[4][4];
#pragma unroll
    for (int i = 0; i < 4; i++)
#pragma unroll
        for (int j = 0; j < 4; j++) acc[i][j] = 0.f;

    int ktiles = 2 * qt + 2;   // columns [0, (qt+1)*64) in steps of 32
    const float* Pbase = g_S + ((size_t)h * Nc + qt * 64) * Nc;

    for (int kt = 0; kt < ktiles; kt++) {
#pragma unroll
        for (int r = 0; r < 8; r++) {
            int idx = tid + 256 * r;
            int rr = idx >> 5;
            int kk = idx & 31;
            Ps[rr][kk] = Pbase[(size_t)rr * Nc + kt * 32 + kk];
        }
#pragma unroll
        for (int r = 0; r < 8; r++) {
            int idx = tid + 256 * r;
            int tok = idx >> 6;
            int d = idx & 63;
            Vs[tok][d] = g_v[(size_t)(kt * 32 + tok) * Dc + h * HDc + d];
        }
        __syncthreads();
#pragma unroll
        for (int kk = 0; kk < 32; kk++) {
            float av[4];
#pragma unroll
            for (int i = 0; i < 4; i++) av[i] = Ps[ty * 4 + i][kk];
            float4 b = *(float4*)&Vs[kk][tx * 4];
            float bv[4] = {b.x, b.y, b.z, b.w};
#pragma unroll
            for (int i = 0; i < 4; i++)
#pragma unroll
                for (int j = 0; j < 4; j++) acc[i][j] = fmaf(av[i], bv[j], acc[i][j]);
        }
        __syncthreads();
    }
#pragma unroll
    for (int i = 0; i < 4; i++) {
        int n = qt * 64 + ty * 4 + i;
        float4 o;
        o.x = acc[i][0]; o.y = acc[i][1]; o.z = acc[i][2]; o.w = acc[i][3];
        *(float4*)&g_ctx[(size_t)n * Dc + h * HDc + tx * 4] = o;
    }
}

// ---------------- act = silu(gate) * up, into g_up ----------------
__global__ __launch_bounds__(256) void silu_kernel()
{
    int idx = blockIdx.x * blockDim.x + threadIdx.x;
    float a = g_gate[idx];
    float s = a / (1.f + expf(-a));
    g_up[idx] = s * g_up[idx];
}

// ---------------- out[b,t,:] = sel + gate_n * (proc - sel) ----------------
__global__ __launch_bounds__(256) void scatter_kernel(
    const int* __restrict__ bi, const int* __restrict__ ti,
    const float* __restrict__ gs, float* __restrict__ out)
{
    int idx = blockIdx.x * blockDim.x + threadIdx.x;   // N*D
    int n = idx >> 10;
    int d = idx & 1023;
    int b = bi[n], t = ti[n];
    float sel = g_sel[idx];
    float p = g_proc[idx];
    out[((size_t)b * Sc + t) * Dc + d] = sel + gs[n] * (p - sel);
}

// ---------------- driver ----------------
extern "C" void kernel_launch(void* const* d_in, const int* in_sizes, int n_in,
                              void* d_out, int out_size)
{
    const float* hidden = (const float*)d_in[0];
    const int*   bi     = (const int*)d_in[1];
    const int*   ti     = (const int*)d_in[2];
    const float* gs     = (const float*)d_in[3];
    const float* cosp   = (const float*)d_in[4];
    const float* sinp   = (const float*)d_in[5];
    const float* Wq     = (const float*)d_in[6];
    const float* bq     = (const float*)d_in[7];
    const float* Wk     = (const float*)d_in[8];
    const float* bk     = (const float*)d_in[9];
    const float* Wv     = (const float*)d_in[10];
    const float* bv     = (const float*)d_in[11];
    const float* Wo     = (const float*)d_in[12];
    const float* Wg     = (const float*)d_in[13];
    const float* Wu     = (const float*)d_in[14];
    const float* Wd     = (const float*)d_in[15];
    const float* ln1    = (const float*)d_in[16];
    const float* ln2    = (const float*)d_in[17];
    float* out = (float*)d_out;

    static float *p_sel = nullptr, *p_h = nullptr, *p_q = nullptr, *p_k = nullptr,
                 *p_v = nullptr, *p_ctx = nullptr, *p_h2 = nullptr, *p_m = nullptr,
                 *p_gate = nullptr, *p_up = nullptr, *p_proc = nullptr;
    if (!p_sel) {
        cudaGetSymbolAddress((void**)&p_sel, g_sel);
        cudaGetSymbolAddress((void**)&p_h, g_h);
        cudaGetSymbolAddress((void**)&p_q, g_q);
        cudaGetSymbolAddress((void**)&p_k, g_k);
        cudaGetSymbolAddress((void**)&p_v, g_v);
        cudaGetSymbolAddress((void**)&p_ctx, g_ctx);
        cudaGetSymbolAddress((void**)&p_h2, g_h2);
        cudaGetSymbolAddress((void**)&p_m, g_m);
        cudaGetSymbolAddress((void**)&p_gate, g_gate);
        cudaGetSymbolAddress((void**)&p_up, g_up);
        cudaGetSymbolAddress((void**)&p_proc, g_proc);
    }

    // 1) copy hidden -> out (scatter overwrites selected rows later)
    cudaMemcpyAsync(out, hidden, sizeof(float) * Bc * Sc * Dc, cudaMemcpyDeviceToDevice);

    // 2) gather + rmsnorm(ln1) + cos/sin gather
    gather_norm_kernel<<<Nc, 256>>>(hidden, bi, ti, cosp, sinp, ln1);

    // 3) QKV fused tf32 GEMM: h @ {Wq,Wk,Wv} + bias   (16 x 24 tiles)
    tgemm_kernel<<<dim3(16, 24), 256>>>(p_h, Dc, Wq, Wk, Wv, bq, bk, bv, nullptr,
                                        p_q, p_k, p_v, Dc, 8);

    // 4) RoPE on q and k
    rope_kernel<<<(2 * Nc * Hc * 32) / 256, 256>>>();

    // 5) scores (lower-triangular tiles)
    scores_kernel<<<dim3(32, 32, Hc), 256>>>();

    // 6) causal softmax in-place
    softmax_kernel<<<dim3(Nc, Hc), 128>>>();

    // 7) ctx = P @ V (causal-bounded)
    ctx_kernel<<<dim3(32, Hc), 256>>>();

    // 8) h2 = sel + ctx @ Wo
    tgemm_kernel<<<dim3(16, 8), 256>>>(p_ctx, Dc, Wo, Wo, Wo,
                                       nullptr, nullptr, nullptr, p_sel,
                                       p_h2, p_h2, p_h2, Dc, 8);

    // 9) m = rmsnorm(h2, ln2)
    rmsnorm2_kernel<<<Nc, 256>>>(ln2);

    // 10) gate/up fused tf32 GEMM: m @ {Wg, Wu}
    tgemm_kernel<<<dim3(16, 64), 256>>>(p_m, Dc, Wg, Wu, Wu,
                                        nullptr, nullptr, nullptr, nullptr,
                                        p_gate, p_up, p_up, Fc, 32);

    // 11) act = silu(gate) * up  (into g_up)
    silu_kernel<<<(Nc * Fc) / 256, 256>>>();

    // 12) proc = h2 + act @ Wd
    tgemm_kernel<<<dim3(16, 8), 256>>>(p_up, Fc, Wd, Wd, Wd,
                                       nullptr, nullptr, nullptr, p_h2,
                                       p_proc, p_proc, p_proc, Dc, 8);

    // 13) gated scatter back
    scatter_kernel<<<(Nc * Dc) / 256, 256>>>(bi, ti, gs, out);
}

// round 4
// speedup vs baseline: 2.6212x; 1.3907x over previous
#include <cuda_runtime.h>
#include <math.h>
#include <stdint.h>

// Problem constants
#define Bc  4
#define Sc  2048
#define Dc  1024
#define Hc  16
#define HDc 64
#define Fc  4096
#define Nc  2048

// ---------------- scratch (__device__ globals; no cudaMalloc allowed) ----------------
__device__ float g_sel[Nc * Dc];
__device__ float g_h[Nc * Dc];
__device__ float g_cg[Nc * HDc];
__device__ float g_sg[Nc * HDc];
__device__ float g_q[Nc * Dc];
__device__ float g_k[Nc * Dc];
__device__ float g_v[Nc * Dc];
__device__ float g_ctx[Nc * Dc];
__device__ float g_h2[Nc * Dc];
__device__ float g_m[Nc * Dc];
__device__ float g_gate[Nc * Fc];
__device__ float g_up[Nc * Fc];               // after silu kernel holds act = silu(g)*u
__device__ float g_proc[Nc * Dc];

// ---------------- tf32 helpers ----------------
__device__ __forceinline__ uint32_t f2tf32(float x) {
    uint32_t r;
    asm("cvt.rna.tf32.f32 %0, %1;" : "=r"(r) : "f"(x));
    return r;
}

__device__ __forceinline__ void mma_tf32(float* c, const uint32_t* a, const uint32_t* b) {
    asm volatile(
        "mma.sync.aligned.m16n8k8.row.col.f32.tf32.tf32.f32 "
        "{%0,%1,%2,%3}, {%4,%5,%6,%7}, {%8,%9}, {%0,%1,%2,%3};"
        : "+f"(c[0]), "+f"(c[1]), "+f"(c[2]), "+f"(c[3])
        : "r"(a[0]), "r"(a[1]), "r"(a[2]), "r"(a[3]), "r"(b[0]), "r"(b[1]));
}

// ---------------- gather + RMSNorm(ln1), plus cos/sin gather ----------------
__global__ __launch_bounds__(256) void gather_norm_kernel(
    const float* __restrict__ hidden, const int* __restrict__ bi,
    const int* __restrict__ ti, const float* __restrict__ cosp,
    const float* __restrict__ sinp, const float* __restrict__ ln1)
{
    int n = blockIdx.x;
    int b = bi[n], t = ti[n];
    const float* row = hidden + ((size_t)b * Sc + t) * Dc;
    float vals[4];
    float local = 0.f;
#pragma unroll
    for (int i = 0; i < 4; i++) {
        float x = row[threadIdx.x + 256 * i];
        vals[i] = x;
        local += x * x;
    }
    __shared__ float red[256];
    red[threadIdx.x] = local;
    __syncthreads();
    for (int s = 128; s > 0; s >>= 1) {
        if (threadIdx.x < s) red[threadIdx.x] += red[threadIdx.x + s];
        __syncthreads();
    }
    float inv = rsqrtf(red[0] / (float)Dc + 1e-6f);
#pragma unroll
    for (int i = 0; i < 4; i++) {
        int d = threadIdx.x + 256 * i;
        g_sel[(size_t)n * Dc + d] = vals[i];
        g_h[(size_t)n * Dc + d] = vals[i] * inv * ln1[d];
    }
    if (threadIdx.x < HDc) {
        size_t src = ((size_t)b * Sc + t) * HDc + threadIdx.x;
        g_cg[n * HDc + threadIdx.x] = cosp[src];
        g_sg[n * HDc + threadIdx.x] = sinp[src];
    }
}

// ---------------- RMSNorm(ln2): g_h2 -> g_m ----------------
__global__ __launch_bounds__(256) void rmsnorm2_kernel(const float* __restrict__ ln2)
{
    int n = blockIdx.x;
    const float* row = g_h2 + (size_t)n * Dc;
    float vals[4];
    float local = 0.f;
#pragma unroll
    for (int i = 0; i < 4; i++) {
        float x = row[threadIdx.x + 256 * i];
        vals[i] = x;
        local += x * x;
    }
    __shared__ float red[256];
    red[threadIdx.x] = local;
    __syncthreads();
    for (int s = 128; s > 0; s >>= 1) {
        if (threadIdx.x < s) red[threadIdx.x] += red[threadIdx.x + s];
        __syncthreads();
    }
    float inv = rsqrtf(red[0] / (float)Dc + 1e-6f);
#pragma unroll
    for (int i = 0; i < 4; i++) {
        int d = threadIdx.x + 256 * i;
        g_m[(size_t)n * Dc + d] = vals[i] * inv * ln2[d];
    }
}

// ---------------- tf32 tensor-core GEMM: C_w = A @ B_w (+bias_w) (+res) ----------------
__global__ __launch_bounds__(256) void tgemm_kernel(
    const float* __restrict__ A, int K,
    const float* __restrict__ B0, const float* __restrict__ B1, const float* __restrict__ B2,
    const float* __restrict__ bias0, const float* __restrict__ bias1, const float* __restrict__ bias2,
    const float* __restrict__ res,
    float* __restrict__ C0, float* __restrict__ C1, float* __restrict__ C2,
    int ldo, int blocksPerW)
{
    int bm = blockIdx.x;
    int by = blockIdx.y;
    int w  = by / blocksPerW;
    int cb = by % blocksPerW;
    const float* B    = (w == 0) ? B0    : (w == 1) ? B1    : B2;
    const float* bias = (w == 0) ? bias0 : (w == 1) ? bias1 : bias2;
    float*       C    = (w == 0) ? C0    : (w == 1) ? C1    : C2;

    __shared__ uint32_t As[128][36];   // [m][k]
    __shared__ uint32_t Bs[32][136];   // [k][n]

    int tid = threadIdx.x;
    int lane = tid & 31;
    int warp = tid >> 5;
    int warpM = warp & 1;
    int warpN = warp >> 1;
    int qr = lane >> 2;
    int qc = lane & 3;

    float acc[4][4][4];
#pragma unroll
    for (int mi = 0; mi < 4; mi++)
#pragma unroll
        for (int ni = 0; ni < 4; ni++)
#pragma unroll
            for (int j = 0; j < 4; j++) acc[mi][ni][j] = 0.f;

    const float* Ablk = A + (size_t)bm * 128 * K;
    const float* Bblk = B + cb * 128;

    for (int kt = 0; kt < K; kt += 32) {
#pragma unroll
        for (int i = 0; i < 4; i++) {
            int idx = tid + 256 * i;
            int row = idx >> 3;
            int c4 = idx & 7;
            float4 v = *(const float4*)&Ablk[(size_t)row * K + kt + c4 * 4];
            As[row][c4 * 4 + 0] = f2tf32(v.x);
            As[row][c4 * 4 + 1] = f2tf32(v.y);
            As[row][c4 * 4 + 2] = f2tf32(v.z);
            As[row][c4 * 4 + 3] = f2tf32(v.w);
        }
#pragma unroll
        for (int i = 0; i < 4; i++) {
            int idx = tid + 256 * i;
            int row = idx >> 5;
            int c4 = idx & 31;
            float4 v = *(const float4*)&Bblk[(size_t)(kt + row) * ldo + c4 * 4];
            Bs[row][c4 * 4 + 0] = f2tf32(v.x);
            Bs[row][c4 * 4 + 1] = f2tf32(v.y);
            Bs[row][c4 * 4 + 2] = f2tf32(v.z);
            Bs[row][c4 * 4 + 3] = f2tf32(v.w);
        }
        __syncthreads();

#pragma unroll
        for (int kk = 0; kk < 4; kk++) {
            int k0 = kk * 8;
            uint32_t a[4][4], b[4][2];
#pragma unroll
            for (int mi = 0; mi < 4; mi++) {
                int r0 = warpM * 64 + mi * 16 + qr;
                a[mi][0] = As[r0][k0 + qc];
                a[mi][1] = As[r0 + 8][k0 + qc];
                a[mi][2] = As[r0][k0 + qc + 4];
                a[mi][3] = As[r0 + 8][k0 + qc + 4];
            }
#pragma unroll
            for (int ni = 0; ni < 4; ni++) {
                int nn = warpN * 32 + ni * 8 + qr;
                b[ni][0] = Bs[k0 + qc][nn];
                b[ni][1] = Bs[k0 + qc + 4][nn];
            }
#pragma unroll
            for (int mi = 0; mi < 4; mi++)
#pragma unroll
                for (int ni = 0; ni < 4; ni++)
                    mma_tf32(acc[mi][ni], a[mi], b[ni]);
        }
        __syncthreads();
    }

#pragma unroll
    for (int mi = 0; mi < 4; mi++) {
#pragma unroll
        for (int ni = 0; ni < 4; ni++) {
            int row = bm * 128 + warpM * 64 + mi * 16 + qr;
            int col = cb * 128 + warpN * 32 + ni * 8 + 2 * qc;
            float2 lo, hi;
            lo.x = acc[mi][ni][0]; lo.y = acc[mi][ni][1];
            hi.x = acc[mi][ni][2]; hi.y = acc[mi][ni][3];
            if (bias) {
                float b0 = bias[col], b1 = bias[col + 1];
                lo.x += b0; lo.y += b1; hi.x += b0; hi.y += b1;
            }
            if (res) {
                const float* r0 = res + (size_t)row * ldo + col;
                const float* r1 = res + (size_t)(row + 8) * ldo + col;
                lo.x += r0[0]; lo.y += r0[1];
                hi.x += r1[0]; hi.y += r1[1];
            }
            *(float2*)&C[(size_t)row * ldo + col] = lo;
            *(float2*)&C[(size_t)(row + 8) * ldo + col] = hi;
        }
    }
}

// ---------------- RoPE in-place on g_q and g_k ----------------
__global__ __launch_bounds__(256) void rope_kernel()
{
    int idx = blockIdx.x * blockDim.x + threadIdx.x;
    int total = Nc * Hc * 32;
    float* buf = (idx < total) ? g_q : g_k;
    int r = idx % total;
    int n = r / (Hc * 32);
    int rem = r % (Hc * 32);
    int h = rem >> 5;
    int d = rem & 31;
    float c1 = g_cg[n * HDc + d],      s1 = g_sg[n * HDc + d];
    float c2 = g_cg[n * HDc + d + 32], s2 = g_sg[n * HDc + d + 32];
    float* p = buf + (size_t)n * Dc + h * HDc;
    float x1 = p[d], x2 = p[d + 32];
    p[d]      = x1 * c1 - x2 * s1;
    p[d + 32] = x2 * c2 + x1 * s2;
}

// ---------------- fused flash attention (tf32 mma, online softmax) ----------------
// 64-row q-tiles; block x = pair index i handles q-tiles i and 31-i (uniform 33
// k-tiles per block). 128 threads = 4 warps; each warp owns 16 q-rows.
// smem: sK [64][68] (natural [key][d]); sV [64][72]; sQ/sP shared region [64][68].
#define FLASH_SMEM ((64*68 + 64*72 + 64*68) * 4)

__global__ __launch_bounds__(128) void flash_kernel()
{
    int pair = blockIdx.x;
    int h = blockIdx.y;
    extern __shared__ uint32_t fsm[];
    uint32_t* sK = fsm;                      // [64][68]
    uint32_t* sV = fsm + 64 * 68;            // [64][72]
    uint32_t* sQ = fsm + 64 * 68 + 64 * 72;  // [64][68], reused per-warp as P
    int tid = threadIdx.x;
    int warp = tid >> 5, lane = tid & 31;
    int qr = lane >> 2, qc = lane & 3;
    uint32_t* sPw = sQ + warp * 16 * 68;

#pragma unroll 1
    for (int pass = 0; pass < 2; pass++) {
        int qt = pass ? (31 - pair) : pair;

        __syncthreads();   // previous pass done with sQ/sP region
        // stage Q tile (64x64) as tf32
#pragma unroll
        for (int i = 0; i < 8; i++) {
            int idx = tid + 128 * i;
            int row = idx >> 4, c4 = idx & 15;
            float4 v = *(const float4*)&g_q[(size_t)(qt * 64 + row) * Dc + h * HDc + c4 * 4];
            uint32_t* d = sQ + row * 68 + c4 * 4;
            d[0] = f2tf32(v.x); d[1] = f2tf32(v.y); d[2] = f2tf32(v.z); d[3] = f2tf32(v.w);
        }
        __syncthreads();

        // Q fragments to registers (warp's 16 rows)
        uint32_t qa[8][4];
        int r0 = warp * 16 + qr;
#pragma unroll
        for (int kf = 0; kf < 8; kf++) {
            int k0 = kf * 8;
            qa[kf][0] = sQ[r0 * 68 + k0 + qc];
            qa[kf][1] = sQ[(r0 + 8) * 68 + k0 + qc];
            qa[kf][2] = sQ[r0 * 68 + k0 + qc + 4];
            qa[kf][3] = sQ[(r0 + 8) * 68 + k0 + qc + 4];
        }
        __syncwarp();

        float m0 = -3e38f, m1 = -3e38f, l0 = 0.f, l1 = 0.f;
        float o[8][4];
#pragma unroll
        for (int ni = 0; ni < 8; ni++)
#pragma unroll
            for (int j = 0; j < 4; j++) o[ni][j] = 0.f;

        int ntiles = qt + 1;
        for (int kt = 0; kt < ntiles; kt++) {
            __syncthreads();   // all warps done reading previous sK/sV
            // load K and V tiles (64 keys x 64 d), natural layout, tf32
#pragma unroll
            for (int i = 0; i < 8; i++) {
                int idx = tid + 128 * i;
                int key = idx >> 4, c4 = idx & 15;
                size_t src = (size_t)(kt * 64 + key) * Dc + h * HDc + c4 * 4;
                float4 kv = *(const float4*)&g_k[src];
                uint32_t* dk = sK + key * 68 + c4 * 4;
                dk[0] = f2tf32(kv.x); dk[1] = f2tf32(kv.y);
                dk[2] = f2tf32(kv.z); dk[3] = f2tf32(kv.w);
                float4 vv = *(const float4*)&g_v[src];
                uint32_t* dv = sV + key * 72 + c4 * 4;
                dv[0] = f2tf32(vv.x); dv[1] = f2tf32(vv.y);
                dv[2] = f2tf32(vv.z); dv[3] = f2tf32(vv.w);
            }
            __syncthreads();

            // S = Q K^T  (B operand: k=d, n=key -> read sK[n][k])
            float s[8][4];
#pragma unroll
            for (int ni = 0; ni < 8; ni++)
#pragma unroll
                for (int j = 0; j < 4; j++) s[ni][j] = 0.f;
#pragma unroll
            for (int kf = 0; kf < 8; kf++) {
                int k0 = kf * 8;
#pragma unroll
                for (int ni = 0; ni < 8; ni++) {
                    uint32_t b[2];
                    b[0] = sK[(8 * ni + qr) * 68 + k0 + qc];
                    b[1] = sK[(8 * ni + qr) * 68 + k0 + qc + 4];
                    mma_tf32(s[ni], qa[kf], b);
                }
            }

            // scale + causal mask (only diagonal tile needs masking)
            bool diag = (kt == qt);
            int rl0 = warp * 16 + qr;        // local row of c0/c1
            int rl1 = rl0 + 8;
#pragma unroll
            for (int ni = 0; ni < 8; ni++) {
                int cl = 8 * ni + 2 * qc;
                s[ni][0] *= 0.125f; s[ni][1] *= 0.125f;
                s[ni][2] *= 0.125f; s[ni][3] *= 0.125f;
                if (diag) {
                    if (cl     > rl0) s[ni][0] = -1e30f;
                    if (cl + 1 > rl0) s[ni][1] = -1e30f;
                    if (cl     > rl1) s[ni][2] = -1e30f;
                    if (cl + 1 > rl1) s[ni][3] = -1e30f;
                }
            }

            // online softmax (rows qr and qr+8)
            float mx0 = -3e38f, mx1 = -3e38f;
#pragma unroll
            for (int ni = 0; ni < 8; ni++) {
                mx0 = fmaxf(mx0, fmaxf(s[ni][0], s[ni][1]));
                mx1 = fmaxf(mx1, fmaxf(s[ni][2], s[ni][3]));
            }
            mx0 = fmaxf(mx0, __shfl_xor_sync(0xffffffff, mx0, 1));
            mx0 = fmaxf(mx0, __shfl_xor_sync(0xffffffff, mx0, 2));
            mx1 = fmaxf(mx1, __shfl_xor_sync(0xffffffff, mx1, 1));
            mx1 = fmaxf(mx1, __shfl_xor_sync(0xffffffff, mx1, 2));
            float mn0 = fmaxf(m0, mx0), mn1 = fmaxf(m1, mx1);
            float sc0 = __expf(m0 - mn0), sc1 = __expf(m1 - mn1);
            m0 = mn0; m1 = mn1;
            float rs0 = 0.f, rs1 = 0.f;
#pragma unroll
            for (int ni = 0; ni < 8; ni++) {
                s[ni][0] = __expf(s[ni][0] - mn0);
                s[ni][1] = __expf(s[ni][1] - mn0);
                s[ni][2] = __expf(s[ni][2] - mn1);
                s[ni][3] = __expf(s[ni][3] - mn1);
                rs0 += s[ni][0] + s[ni][1];
                rs1 += s[ni][2] + s[ni][3];
            }
            rs0 += __shfl_xor_sync(0xffffffff, rs0, 1);
            rs0 += __shfl_xor_sync(0xffffffff, rs0, 2);
            rs1 += __shfl_xor_sync(0xffffffff, rs1, 1);
            rs1 += __shfl_xor_sync(0xffffffff, rs1, 2);
            l0 = l0 * sc0 + rs0;
            l1 = l1 * sc1 + rs1;
#pragma unroll
            for (int ni = 0; ni < 8; ni++) {
                o[ni][0] *= sc0; o[ni][1] *= sc0;
                o[ni][2] *= sc1; o[ni][3] *= sc1;
            }

            // store P (tf32) to per-warp smem region
#pragma unroll
            for (int ni = 0; ni < 8; ni++) {
                int cl = 8 * ni + 2 * qc;
                sPw[qr * 68 + cl]           = f2tf32(s[ni][0]);
                sPw[qr * 68 + cl + 1]       = f2tf32(s[ni][1]);
                sPw[(qr + 8) * 68 + cl]     = f2tf32(s[ni][2]);
                sPw[(qr + 8) * 68 + cl + 1] = f2tf32(s[ni][3]);
            }
            __syncwarp();

            // O += P @ V  (B operand: k=key, n=d -> read sV[k][n])
#pragma unroll
            for (int kf = 0; kf < 8; kf++) {
                int k0 = kf * 8;
                uint32_t a[4];
                a[0] = sPw[qr * 68 + k0 + qc];
                a[1] = sPw[(qr + 8) * 68 + k0 + qc];
                a[2] = sPw[qr * 68 + k0 + qc + 4];
                a[3] = sPw[(qr + 8) * 68 + k0 + qc + 4];
#pragma unroll
                for (int ni = 0; ni < 8; ni++) {
                    uint32_t b[2];
                    b[0] = sV[(k0 + qc) * 72 + 8 * ni + qr];
                    b[1] = sV[(k0 + qc + 4) * 72 + 8 * ni + qr];
                    mma_tf32(o[ni], a, b);
                }
            }
            __syncwarp();   // P reads done before next tile's P writes
        }

        // epilogue: normalize and write ctx
        float li0 = 1.f / l0, li1 = 1.f / l1;
        int rg0 = qt * 64 + warp * 16 + qr;
#pragma unroll
        for (int ni = 0; ni < 8; ni++) {
            int col = h * HDc + 8 * ni + 2 * qc;
            float2 lo, hi;
            lo.x = o[ni][0] * li0; lo.y = o[ni][1] * li0;
            hi.x = o[ni][2] * li1; hi.y = o[ni][3] * li1;
            *(float2*)&g_ctx[(size_t)rg0 * Dc + col] = lo;
            *(float2*)&g_ctx[(size_t)(rg0 + 8) * Dc + col] = hi;
        }
    }
}

// ---------------- act = silu(gate) * up, into g_up ----------------
__global__ __launch_bounds__(256) void silu_kernel()
{
    int idx = blockIdx.x * blockDim.x + threadIdx.x;
    float a = g_gate[idx];
    float s = a / (1.f + expf(-a));
    g_up[idx] = s * g_up[idx];
}

// ---------------- out[b,t,:] = sel + gate_n * (proc - sel) ----------------
__global__ __launch_bounds__(256) void scatter_kernel(
    const int* __restrict__ bi, const int* __restrict__ ti,
    const float* __restrict__ gs, float* __restrict__ out)
{
    int idx = blockIdx.x * blockDim.x + threadIdx.x;
    int n = idx >> 10;
    int d = idx & 1023;
    int b = bi[n], t = ti[n];
    float sel = g_sel[idx];
    float p = g_proc[idx];
    out[((size_t)b * Sc + t) * Dc + d] = sel + gs[n] * (p - sel);
}

// ---------------- driver ----------------
extern "C" void kernel_launch(void* const* d_in, const int* in_sizes, int n_in,
                              void* d_out, int out_size)
{
    const float* hidden = (const float*)d_in[0];
    const int*   bi     = (const int*)d_in[1];
    const int*   ti     = (const int*)d_in[2];
    const float* gs     = (const float*)d_in[3];
    const float* cosp   = (const float*)d_in[4];
    const float* sinp   = (const float*)d_in[5];
    const float* Wq     = (const float*)d_in[6];
    const float* bq     = (const float*)d_in[7];
    const float* Wk     = (const float*)d_in[8];
    const float* bk     = (const float*)d_in[9];
    const float* Wv     = (const float*)d_in[10];
    const float* bv     = (const float*)d_in[11];
    const float* Wo     = (const float*)d_in[12];
    const float* Wg     = (const float*)d_in[13];
    const float* Wu     = (const float*)d_in[14];
    const float* Wd     = (const float*)d_in[15];
    const float* ln1    = (const float*)d_in[16];
    const float* ln2    = (const float*)d_in[17];
    float* out = (float*)d_out;

    static float *p_sel = nullptr, *p_h = nullptr, *p_q = nullptr, *p_k = nullptr,
                 *p_v = nullptr, *p_ctx = nullptr, *p_h2 = nullptr, *p_m = nullptr,
                 *p_gate = nullptr, *p_up = nullptr, *p_proc = nullptr;
    static bool inited = false;
    if (!inited) {
        cudaGetSymbolAddress((void**)&p_sel, g_sel);
        cudaGetSymbolAddress((void**)&p_h, g_h);
        cudaGetSymbolAddress((void**)&p_q, g_q);
        cudaGetSymbolAddress((void**)&p_k, g_k);
        cudaGetSymbolAddress((void**)&p_v, g_v);
        cudaGetSymbolAddress((void**)&p_ctx, g_ctx);
        cudaGetSymbolAddress((void**)&p_h2, g_h2);
        cudaGetSymbolAddress((void**)&p_m, g_m);
        cudaGetSymbolAddress((void**)&p_gate, g_gate);
        cudaGetSymbolAddress((void**)&p_up, g_up);
        cudaGetSymbolAddress((void**)&p_proc, g_proc);
        cudaFuncSetAttribute(flash_kernel,
                             cudaFuncAttributeMaxDynamicSharedMemorySize, FLASH_SMEM);
        inited = true;
    }

    // 1) copy hidden -> out (scatter overwrites selected rows later)
    cudaMemcpyAsync(out, hidden, sizeof(float) * Bc * Sc * Dc, cudaMemcpyDeviceToDevice);

    // 2) gather + rmsnorm(ln1) + cos/sin gather
    gather_norm_kernel<<<Nc, 256>>>(hidden, bi, ti, cosp, sinp, ln1);

    // 3) QKV fused tf32 GEMM: h @ {Wq,Wk,Wv} + bias
    tgemm_kernel<<<dim3(16, 24), 256>>>(p_h, Dc, Wq, Wk, Wv, bq, bk, bv, nullptr,
                                        p_q, p_k, p_v, Dc, 8);

    // 4) RoPE on q and k
    rope_kernel<<<(2 * Nc * Hc * 32) / 256, 256>>>();

    // 5) fused flash attention -> g_ctx
    flash_kernel<<<dim3(16, Hc), 128, FLASH_SMEM>>>();

    // 6) h2 = sel + ctx @ Wo
    tgemm_kernel<<<dim3(16, 8), 256>>>(p_ctx, Dc, Wo, Wo, Wo,
                                       nullptr, nullptr, nullptr, p_sel,
                                       p_h2, p_h2, p_h2, Dc, 8);

    // 7) m = rmsnorm(h2, ln2)
    rmsnorm2_kernel<<<Nc, 256>>>(ln2);

    // 8) gate/up fused tf32 GEMM: m @ {Wg, Wu}
    tgemm_kernel<<<dim3(16, 64), 256>>>(p_m, Dc, Wg, Wu, Wu,
                                        nullptr, nullptr, nullptr, nullptr,
                                        p_gate, p_up, p_up, Fc, 32);

    // 9) act = silu(gate) * up  (into g_up)
    silu_kernel<<<(Nc * Fc) / 256, 256>>>();

    // 10) proc = h2 + act @ Wd
    tgemm_kernel<<<dim3(16, 8), 256>>>(p_up, Fc, Wd, Wd, Wd,
                                       nullptr, nullptr, nullptr, p_h2,
                                       p_proc, p_proc, p_proc, Dc, 8);

    // 11) gated scatter back
    scatter_kernel<<<(Nc * Dc) / 256, 256>>>(bi, ti, gs, out);
}

// round 5
// speedup vs baseline: 3.4080x; 1.3002x over previous
#include <cuda_runtime.h>
#include <math.h>
#include <stdint.h>

// Problem constants
#define Bc  4
#define Sc  2048
#define Dc  1024
#define Hc  16
#define HDc 64
#define Fc  4096
#define Nc  2048

// ---------------- scratch (__device__ globals; no cudaMalloc allowed) ----------------
__device__ float g_sel[Nc * Dc];
__device__ float g_h[Nc * Dc];
__device__ float g_cg[Nc * HDc];
__device__ float g_sg[Nc * HDc];
__device__ float g_q[Nc * Dc];
__device__ float g_k[Nc * Dc];
__device__ float g_v[Nc * Dc];
__device__ float g_ctx[Nc * Dc];
__device__ float g_h2[Nc * Dc];
__device__ float g_m[Nc * Dc];
__device__ float g_gate[Nc * Fc];
__device__ float g_up[Nc * Fc];
__device__ float g_proc[Nc * Dc];

// ---------------- helpers ----------------
__device__ __forceinline__ uint32_t sptr(const void* p) {
    return (uint32_t)__cvta_generic_to_shared(p);
}
__device__ __forceinline__ void cp16(uint32_t s, const void* g) {
    asm volatile("cp.async.cg.shared.global [%0], [%1], 16;\n" :: "r"(s), "l"(g));
}
__device__ __forceinline__ void cp_commit() { asm volatile("cp.async.commit_group;\n"); }
template<int W> __device__ __forceinline__ void cp_wait() {
    asm volatile("cp.async.wait_group %0;\n" :: "n"(W));
}

// raw fp32 bits fed to tf32 mma: HW truncates mantissa to tf32 precision.
__device__ __forceinline__ void mma_tf32(float* c, const uint32_t* a, const uint32_t* b) {
    asm volatile(
        "mma.sync.aligned.m16n8k8.row.col.f32.tf32.tf32.f32 "
        "{%0,%1,%2,%3}, {%4,%5,%6,%7}, {%8,%9}, {%0,%1,%2,%3};"
        : "+f"(c[0]), "+f"(c[1]), "+f"(c[2]), "+f"(c[3])
        : "r"(a[0]), "r"(a[1]), "r"(a[2]), "r"(a[3]), "r"(b[0]), "r"(b[1]));
}

// ---------------- gather + RMSNorm(ln1), plus cos/sin gather ----------------
__global__ __launch_bounds__(256) void gather_norm_kernel(
    const float* __restrict__ hidden, const int* __restrict__ bi,
    const int* __restrict__ ti, const float* __restrict__ cosp,
    const float* __restrict__ sinp, const float* __restrict__ ln1)
{
    int n = blockIdx.x;
    int b = bi[n], t = ti[n];
    const float* row = hidden + ((size_t)b * Sc + t) * Dc;
    float vals[4];
    float local = 0.f;
#pragma unroll
    for (int i = 0; i < 4; i++) {
        float x = row[threadIdx.x + 256 * i];
        vals[i] = x;
        local += x * x;
    }
    __shared__ float red[256];
    red[threadIdx.x] = local;
    __syncthreads();
    for (int s = 128; s > 0; s >>= 1) {
        if (threadIdx.x < s) red[threadIdx.x] += red[threadIdx.x + s];
        __syncthreads();
    }
    float inv = rsqrtf(red[0] / (float)Dc + 1e-6f);
#pragma unroll
    for (int i = 0; i < 4; i++) {
        int d = threadIdx.x + 256 * i;
        g_sel[(size_t)n * Dc + d] = vals[i];
        g_h[(size_t)n * Dc + d] = vals[i] * inv * ln1[d];
    }
    if (threadIdx.x < HDc) {
        size_t src = ((size_t)b * Sc + t) * HDc + threadIdx.x;
        g_cg[n * HDc + threadIdx.x] = cosp[src];
        g_sg[n * HDc + threadIdx.x] = sinp[src];
    }
}

// ---------------- RMSNorm(ln2): g_h2 -> g_m ----------------
__global__ __launch_bounds__(256) void rmsnorm2_kernel(const float* __restrict__ ln2)
{
    int n = blockIdx.x;
    const float* row = g_h2 + (size_t)n * Dc;
    float vals[4];
    float local = 0.f;
#pragma unroll
    for (int i = 0; i < 4; i++) {
        float x = row[threadIdx.x + 256 * i];
        vals[i] = x;
        local += x * x;
    }
    __shared__ float red[256];
    red[threadIdx.x] = local;
    __syncthreads();
    for (int s = 128; s > 0; s >>= 1) {
        if (threadIdx.x < s) red[threadIdx.x] += red[threadIdx.x + s];
        __syncthreads();
    }
    float inv = rsqrtf(red[0] / (float)Dc + 1e-6f);
#pragma unroll
    for (int i = 0; i < 4; i++) {
        int d = threadIdx.x + 256 * i;
        g_m[(size_t)n * Dc + d] = vals[i] * inv * ln2[d];
    }
}

// ---------------- pipelined tf32 GEMM: C_w = A @ B_w (+bias_w) (+res) ----------------
// Block tile 128 x BN (BN = NI*32), BK=32, 256 threads, 8 warps (2x4),
// warp tile 64 x (NI*8). 2-stage cp.async double buffer, raw-fp32 tf32 mma.
template<int NI>
__global__ __launch_bounds__(256) void tgemm_kernel(
    const float* __restrict__ A, int K,
    const float* __restrict__ B0, const float* __restrict__ B1, const float* __restrict__ B2,
    const float* __restrict__ bias0, const float* __restrict__ bias1, const float* __restrict__ bias2,
    const float* __restrict__ res,
    float* __restrict__ C0, float* __restrict__ C1, float* __restrict__ C2,
    int ldo, int blocksPerW)
{
    constexpr int BN  = NI * 32;
    constexpr int BS  = BN + 8;        // B smem row stride
    constexpr int BN4 = BN / 4;
    constexpr int ABUF = 2 * 128 * 36; // uint32 units

    int bm = blockIdx.x;
    int by = blockIdx.y;
    int w  = by / blocksPerW;
    int cb = by % blocksPerW;
    const float* B    = (w == 0) ? B0    : (w == 1) ? B1    : B2;
    const float* bias = (w == 0) ? bias0 : (w == 1) ? bias1 : bias2;
    float*       C    = (w == 0) ? C0    : (w == 1) ? C1    : C2;

    extern __shared__ uint32_t ts[];
    uint32_t sbase = sptr(ts);

    int tid = threadIdx.x;
    int lane = tid & 31;
    int warp = tid >> 5;
    int warpM = warp & 1;
    int warpN = warp >> 1;
    int qr = lane >> 2;
    int qc = lane & 3;

    float acc[4][NI][4];
#pragma unroll
    for (int mi = 0; mi < 4; mi++)
#pragma unroll
        for (int ni = 0; ni < NI; ni++)
#pragma unroll
            for (int j = 0; j < 4; j++) acc[mi][ni][j] = 0.f;

    const float* Ablk = A + (size_t)bm * 128 * K;
    const float* Bblk = B + cb * BN;

    int nk = K >> 5;

    // issue tile kt into buffer buf
    auto issue = [&](int kt, int buf) {
#pragma unroll
        for (int i = 0; i < 4; i++) {
            int idx = tid + 256 * i;
            int row = idx >> 3;
            int c4 = idx & 7;
            cp16(sbase + (buf * 128 * 36 + row * 36 + c4 * 4) * 4,
                 &Ablk[(size_t)row * K + kt * 32 + c4 * 4]);
        }
#pragma unroll
        for (int i = 0; i < NI; i++) {
            int idx = tid + 256 * i;
            int row = idx / BN4;
            int c = idx % BN4;
            cp16(sbase + (ABUF + buf * 32 * BS + row * BS + c * 4) * 4,
                 &Bblk[(size_t)(kt * 32 + row) * ldo + c * 4]);
        }
        cp_commit();
    };

    issue(0, 0);

    for (int kt = 0; kt < nk; kt++) {
        if (kt + 1 < nk) { issue(kt + 1, (kt + 1) & 1); cp_wait<1>(); }
        else cp_wait<0>();
        __syncthreads();

        const uint32_t* Ab = ts + (kt & 1) * 128 * 36;
        const uint32_t* Bb = ts + ABUF + (kt & 1) * 32 * BS;
#pragma unroll
        for (int kk = 0; kk < 4; kk++) {
            int k0 = kk * 8;
            uint32_t a[4][4], b[NI][2];
#pragma unroll
            for (int mi = 0; mi < 4; mi++) {
                int r0 = warpM * 64 + mi * 16 + qr;
                a[mi][0] = Ab[r0 * 36 + k0 + qc];
                a[mi][1] = Ab[(r0 + 8) * 36 + k0 + qc];
                a[mi][2] = Ab[r0 * 36 + k0 + qc + 4];
                a[mi][3] = Ab[(r0 + 8) * 36 + k0 + qc + 4];
            }
#pragma unroll
            for (int ni = 0; ni < NI; ni++) {
                int nn = warpN * (NI * 8) + ni * 8 + qr;
                b[ni][0] = Bb[(k0 + qc) * BS + nn];
                b[ni][1] = Bb[(k0 + qc + 4) * BS + nn];
            }
#pragma unroll
            for (int mi = 0; mi < 4; mi++)
#pragma unroll
                for (int ni = 0; ni < NI; ni++)
                    mma_tf32(acc[mi][ni], a[mi], b[ni]);
        }
        __syncthreads();
    }

#pragma unroll
    for (int mi = 0; mi < 4; mi++) {
#pragma unroll
        for (int ni = 0; ni < NI; ni++) {
            int row = bm * 128 + warpM * 64 + mi * 16 + qr;
            int col = cb * BN + warpN * (NI * 8) + ni * 8 + 2 * qc;
            float2 lo, hi;
            lo.x = acc[mi][ni][0]; lo.y = acc[mi][ni][1];
            hi.x = acc[mi][ni][2]; hi.y = acc[mi][ni][3];
            if (bias) {
                float b0 = bias[col], b1 = bias[col + 1];
                lo.x += b0; lo.y += b1; hi.x += b0; hi.y += b1;
            }
            if (res) {
                const float* r0 = res + (size_t)row * ldo + col;
                const float* r1 = res + (size_t)(row + 8) * ldo + col;
                lo.x += r0[0]; lo.y += r0[1];
                hi.x += r1[0]; hi.y += r1[1];
            }
            *(float2*)&C[(size_t)row * ldo + col] = lo;
            *(float2*)&C[(size_t)(row + 8) * ldo + col] = hi;
        }
    }
}

#define TG_SMEM_128 ((2*128*36 + 2*32*136) * 4)
#define TG_SMEM_64  ((2*128*36 + 2*32*72) * 4)

// ---------------- RoPE in-place on g_q and g_k ----------------
__global__ __launch_bounds__(256) void rope_kernel()
{
    int idx = blockIdx.x * blockDim.x + threadIdx.x;
    int total = Nc * Hc * 32;
    float* buf = (idx < total) ? g_q : g_k;
    int r = idx % total;
    int n = r / (Hc * 32);
    int rem = r % (Hc * 32);
    int h = rem >> 5;
    int d = rem & 31;
    float c1 = g_cg[n * HDc + d],      s1 = g_sg[n * HDc + d];
    float c2 = g_cg[n * HDc + d + 32], s2 = g_sg[n * HDc + d + 32];
    float* p = buf + (size_t)n * Dc + h * HDc;
    float x1 = p[d], x2 = p[d + 32];
    p[d]      = x1 * c1 - x2 * s1;
    p[d + 32] = x2 * c2 + x1 * s2;
}

// ---------------- fused flash attention (tf32 mma, online softmax) ----------------
// Double-buffered cp.async K/V. Block x = pair i handles q-tiles i and 31-i.
// smem layout (uint32 units): sK[2]@0,4352  sV[2]@8704,13312  sQ/P@17920
#define FK(buf) ((buf) * 4352)
#define FV(buf) (8704 + (buf) * 4608)
#define FQ      17920
#define FLASH_SMEM ((2*64*68 + 2*64*72 + 64*68) * 4)

__global__ __launch_bounds__(128) void flash_kernel()
{
    int pair = blockIdx.x;
    int h = blockIdx.y;
    extern __shared__ uint32_t fsm[];
    uint32_t sbase = sptr(fsm);
    int tid = threadIdx.x;
    int warp = tid >> 5, lane = tid & 31;
    int qr = lane >> 2, qc = lane & 3;
    uint32_t* sQ = fsm + FQ;
    uint32_t* sPw = sQ + warp * 16 * 68;

    auto issue_kv = [&](int kt, int buf) {
#pragma unroll
        for (int i = 0; i < 8; i++) {
            int idx = tid + 128 * i;
            int key = idx >> 4, c4 = idx & 15;
            size_t src = (size_t)(kt * 64 + key) * Dc + h * HDc + c4 * 4;
            cp16(sbase + (FK(buf) + key * 68 + c4 * 4) * 4, &g_k[src]);
            cp16(sbase + (FV(buf) + key * 72 + c4 * 4) * 4, &g_v[src]);
        }
        cp_commit();
    };

#pragma unroll 1
    for (int pass = 0; pass < 2; pass++) {
        int qt = pass ? (31 - pair) : pair;

        __syncthreads();   // previous pass done with smem
        // stage Q tile (64x64), raw fp32 bits
#pragma unroll
        for (int i = 0; i < 8; i++) {
            int idx = tid + 128 * i;
            int row = idx >> 4, c4 = idx & 15;
            uint4 v = *(const uint4*)&g_q[(size_t)(qt * 64 + row) * Dc + h * HDc + c4 * 4];
            *(uint4*)&sQ[row * 68 + c4 * 4] = v;
        }
        __syncthreads();

        // Q fragments to registers (warp's 16 rows)
        uint32_t qa[8][4];
        int r0 = warp * 16 + qr;
#pragma unroll
        for (int kf = 0; kf < 8; kf++) {
            int k0 = kf * 8;
            qa[kf][0] = sQ[r0 * 68 + k0 + qc];
            qa[kf][1] = sQ[(r0 + 8) * 68 + k0 + qc];
            qa[kf][2] = sQ[r0 * 68 + k0 + qc + 4];
            qa[kf][3] = sQ[(r0 + 8) * 68 + k0 + qc + 4];
        }
        __syncthreads();   // all warps got Q frags; sQ free for P reuse

        float m0 = -3e38f, m1 = -3e38f, l0 = 0.f, l1 = 0.f;
        float o[8][4];
#pragma unroll
        for (int ni = 0; ni < 8; ni++)
#pragma unroll
            for (int j = 0; j < 4; j++) o[ni][j] = 0.f;

        int ntiles = qt + 1;
        issue_kv(0, 0);
        for (int kt = 0; kt < ntiles; kt++) {
            if (kt + 1 < ntiles) { issue_kv(kt + 1, (kt + 1) & 1); cp_wait<1>(); }
            else cp_wait<0>();
            __syncthreads();
            const uint32_t* sK = fsm + FK(kt & 1);
            const uint32_t* sV = fsm + FV(kt & 1);

            // S = Q K^T
            float s[8][4];
#pragma unroll
            for (int ni = 0; ni < 8; ni++)
#pragma unroll
                for (int j = 0; j < 4; j++) s[ni][j] = 0.f;
#pragma unroll
            for (int kf = 0; kf < 8; kf++) {
                int k0 = kf * 8;
#pragma unroll
                for (int ni = 0; ni < 8; ni++) {
                    uint32_t b[2];
                    b[0] = sK[(8 * ni + qr) * 68 + k0 + qc];
                    b[1] = sK[(8 * ni + qr) * 68 + k0 + qc + 4];
                    mma_tf32(s[ni], qa[kf], b);
                }
            }

            // scale + causal mask (diagonal tile only)
            bool diag = (kt == qt);
            int rl0 = warp * 16 + qr;
            int rl1 = rl0 + 8;
#pragma unroll
            for (int ni = 0; ni < 8; ni++) {
                int cl = 8 * ni + 2 * qc;
                s[ni][0] *= 0.125f; s[ni][1] *= 0.125f;
                s[ni][2] *= 0.125f; s[ni][3] *= 0.125f;
                if (diag) {
                    if (cl     > rl0) s[ni][0] = -1e30f;
                    if (cl + 1 > rl0) s[ni][1] = -1e30f;
                    if (cl     > rl1) s[ni][2] = -1e30f;
                    if (cl + 1 > rl1) s[ni][3] = -1e30f;
                }
            }

            // online softmax
            float mx0 = -3e38f, mx1 = -3e38f;
#pragma unroll
            for (int ni = 0; ni < 8; ni++) {
                mx0 = fmaxf(mx0, fmaxf(s[ni][0], s[ni][1]));
                mx1 = fmaxf(mx1, fmaxf(s[ni][2], s[ni][3]));
            }
            mx0 = fmaxf(mx0, __shfl_xor_sync(0xffffffff, mx0, 1));
            mx0 = fmaxf(mx0, __shfl_xor_sync(0xffffffff, mx0, 2));
            mx1 = fmaxf(mx1, __shfl_xor_sync(0xffffffff, mx1, 1));
            mx1 = fmaxf(mx1, __shfl_xor_sync(0xffffffff, mx1, 2));
            float mn0 = fmaxf(m0, mx0), mn1 = fmaxf(m1, mx1);
            float sc0 = __expf(m0 - mn0), sc1 = __expf(m1 - mn1);
            m0 = mn0; m1 = mn1;
            float rs0 = 0.f, rs1 = 0.f;
#pragma unroll
            for (int ni = 0; ni < 8; ni++) {
                s[ni][0] = __expf(s[ni][0] - mn0);
                s[ni][1] = __expf(s[ni][1] - mn0);
                s[ni][2] = __expf(s[ni][2] - mn1);
                s[ni][3] = __expf(s[ni][3] - mn1);
                rs0 += s[ni][0] + s[ni][1];
                rs1 += s[ni][2] + s[ni][3];
            }
            rs0 += __shfl_xor_sync(0xffffffff, rs0, 1);
            rs0 += __shfl_xor_sync(0xffffffff, rs0, 2);
            rs1 += __shfl_xor_sync(0xffffffff, rs1, 1);
            rs1 += __shfl_xor_sync(0xffffffff, rs1, 2);
            l0 = l0 * sc0 + rs0;
            l1 = l1 * sc1 + rs1;
#pragma unroll
            for (int ni = 0; ni < 8; ni++) {
                o[ni][0] *= sc0; o[ni][1] *= sc0;
                o[ni][2] *= sc1; o[ni][3] *= sc1;
            }

            // store P (raw fp32) to per-warp smem region
#pragma unroll
            for (int ni = 0; ni < 8; ni++) {
                int cl = 8 * ni + 2 * qc;
                sPw[qr * 68 + cl]           = __float_as_uint(s[ni][0]);
                sPw[qr * 68 + cl + 1]       = __float_as_uint(s[ni][1]);
                sPw[(qr + 8) * 68 + cl]     = __float_as_uint(s[ni][2]);
                sPw[(qr + 8) * 68 + cl + 1] = __float_as_uint(s[ni][3]);
            }
            __syncwarp();

            // O += P @ V
#pragma unroll
            for (int kf = 0; kf < 8; kf++) {
                int k0 = kf * 8;
                uint32_t a[4];
                a[0] = sPw[qr * 68 + k0 + qc];
                a[1] = sPw[(qr + 8) * 68 + k0 + qc];
                a[2] = sPw[qr * 68 + k0 + qc + 4];
                a[3] = sPw[(qr + 8) * 68 + k0 + qc + 4];
#pragma unroll
                for (int ni = 0; ni < 8; ni++) {
                    uint32_t b[2];
                    b[0] = sV[(k0 + qc) * 72 + 8 * ni + qr];
                    b[1] = sV[(k0 + qc + 4) * 72 + 8 * ni + qr];
                    mma_tf32(o[ni], a, b);
                }
            }
            __syncthreads();   // done with this tile's buffers before overwrite
        }

        // epilogue: normalize and write ctx
        float li0 = 1.f / l0, li1 = 1.f / l1;
        int rg0 = qt * 64 + warp * 16 + qr;
#pragma unroll
        for (int ni = 0; ni < 8; ni++) {
            int col = h * HDc + 8 * ni + 2 * qc;
            float2 lo, hi;
            lo.x = o[ni][0] * li0; lo.y = o[ni][1] * li0;
            hi.x = o[ni][2] * li1; hi.y = o[ni][3] * li1;
            *(float2*)&g_ctx[(size_t)rg0 * Dc + col] = lo;
            *(float2*)&g_ctx[(size_t)(rg0 + 8) * Dc + col] = hi;
        }
    }
}

// ---------------- act = silu(gate) * up, into g_up (float4) ----------------
__global__ __launch_bounds__(256) void silu_kernel()
{
    int idx = blockIdx.x * blockDim.x + threadIdx.x;
    float4 a = ((const float4*)g_gate)[idx];
    float4 u = ((const float4*)g_up)[idx];
    u.x *= a.x / (1.f + __expf(-a.x));
    u.y *= a.y / (1.f + __expf(-a.y));
    u.z *= a.z / (1.f + __expf(-a.z));
    u.w *= a.w / (1.f + __expf(-a.w));
    ((float4*)g_up)[idx] = u;
}

// ---------------- out[b,t,:] = sel + gate_n * (proc - sel) ----------------
__global__ __launch_bounds__(256) void scatter_kernel(
    const int* __restrict__ bi, const int* __restrict__ ti,
    const float* __restrict__ gs, float* __restrict__ out)
{
    int idx = blockIdx.x * blockDim.x + threadIdx.x;
    int n = idx >> 10;
    int d = idx & 1023;
    int b = bi[n], t = ti[n];
    float sel = g_sel[idx];
    float p = g_proc[idx];
    out[((size_t)b * Sc + t) * Dc + d] = sel + gs[n] * (p - sel);
}

// ---------------- driver ----------------
extern "C" void kernel_launch(void* const* d_in, const int* in_sizes, int n_in,
                              void* d_out, int out_size)
{
    const float* hidden = (const float*)d_in[0];
    const int*   bi     = (const int*)d_in[1];
    const int*   ti     = (const int*)d_in[2];
    const float* gs     = (const float*)d_in[3];
    const float* cosp   = (const float*)d_in[4];
    const float* sinp   = (const float*)d_in[5];
    const float* Wq     = (const float*)d_in[6];
    const float* bq     = (const float*)d_in[7];
    const float* Wk     = (const float*)d_in[8];
    const float* bk     = (const float*)d_in[9];
    const float* Wv     = (const float*)d_in[10];
    const float* bv     = (const float*)d_in[11];
    const float* Wo     = (const float*)d_in[12];
    const float* Wg     = (const float*)d_in[13];
    const float* Wu     = (const float*)d_in[14];
    const float* Wd     = (const float*)d_in[15];
    const float* ln1    = (const float*)d_in[16];
    const float* ln2    = (const float*)d_in[17];
    float* out = (float*)d_out;

    static float *p_sel = nullptr, *p_h = nullptr, *p_q = nullptr, *p_k = nullptr,
                 *p_v = nullptr, *p_ctx = nullptr, *p_h2 = nullptr, *p_m = nullptr,
                 *p_gate = nullptr, *p_up = nullptr, *p_proc = nullptr;
    static bool inited = false;
    if (!inited) {
        cudaGetSymbolAddress((void**)&p_sel, g_sel);
        cudaGetSymbolAddress((void**)&p_h, g_h);
        cudaGetSymbolAddress((void**)&p_q, g_q);
        cudaGetSymbolAddress((void**)&p_k, g_k);
        cudaGetSymbolAddress((void**)&p_v, g_v);
        cudaGetSymbolAddress((void**)&p_ctx, g_ctx);
        cudaGetSymbolAddress((void**)&p_h2, g_h2);
        cudaGetSymbolAddress((void**)&p_m, g_m);
        cudaGetSymbolAddress((void**)&p_gate, g_gate);
        cudaGetSymbolAddress((void**)&p_up, g_up);
        cudaGetSymbolAddress((void**)&p_proc, g_proc);
        cudaFuncSetAttribute(flash_kernel,
                             cudaFuncAttributeMaxDynamicSharedMemorySize, FLASH_SMEM);
        cudaFuncSetAttribute(tgemm_kernel<4>,
                             cudaFuncAttributeMaxDynamicSharedMemorySize, TG_SMEM_128);
        cudaFuncSetAttribute(tgemm_kernel<2>,
                             cudaFuncAttributeMaxDynamicSharedMemorySize, TG_SMEM_64);
        inited = true;
    }

    // 1) copy hidden -> out (scatter overwrites selected rows later)
    cudaMemcpyAsync(out, hidden, sizeof(float) * Bc * Sc * Dc, cudaMemcpyDeviceToDevice);

    // 2) gather + rmsnorm(ln1) + cos/sin gather
    gather_norm_kernel<<<Nc, 256>>>(hidden, bi, ti, cosp, sinp, ln1);

    // 3) QKV fused tf32 GEMM: h @ {Wq,Wk,Wv} + bias  (BN=128)
    tgemm_kernel<4><<<dim3(16, 24), 256, TG_SMEM_128>>>(
        p_h, Dc, Wq, Wk, Wv, bq, bk, bv, nullptr, p_q, p_k, p_v, Dc, 8);

    // 4) RoPE on q and k
    rope_kernel<<<(2 * Nc * Hc * 32) / 256, 256>>>();

    // 5) fused flash attention -> g_ctx
    flash_kernel<<<dim3(16, Hc), 128, FLASH_SMEM>>>();

    // 6) h2 = sel + ctx @ Wo  (BN=64 -> 256 blocks, fills the chip)
    tgemm_kernel<2><<<dim3(16, 16), 256, TG_SMEM_64>>>(
        p_ctx, Dc, Wo, Wo, Wo, nullptr, nullptr, nullptr, p_sel,
        p_h2, p_h2, p_h2, Dc, 16);

    // 7) m = rmsnorm(h2, ln2)
    rmsnorm2_kernel<<<Nc, 256>>>(ln2);

    // 8) gate/up fused tf32 GEMM: m @ {Wg, Wu}  (BN=128)
    tgemm_kernel<4><<<dim3(16, 64), 256, TG_SMEM_128>>>(
        p_m, Dc, Wg, Wu, Wu, nullptr, nullptr, nullptr, nullptr,
        p_gate, p_up, p_up, Fc, 32);

    // 9) act = silu(gate) * up  (into g_up)
    silu_kernel<<<(Nc * Fc / 4) / 256, 256>>>();

    // 10) proc = h2 + act @ Wd  (BN=64 -> 256 blocks)
    tgemm_kernel<2><<<dim3(16, 16), 256, TG_SMEM_64>>>(
        p_up, Fc, Wd, Wd, Wd, nullptr, nullptr, nullptr, p_h2,
        p_proc, p_proc, p_proc, Dc, 16);

    // 11) gated scatter back
    scatter_kernel<<<(Nc * Dc) / 256, 256>>>(bi, ti, gs, out);
}